// round 4
// baseline (speedup 1.0000x reference)
#include <cuda_runtime.h>
#include <math.h>

#define NN 100000
#define NE 1600000
#define DH 128
#define NC 64

// ---- persistent scratch (no allocations allowed) ----
__device__ int   g_deg[NN];
__device__ float g_inv[NN];
__device__ int   g_rp[NN + 1];
__device__ int   g_cur[NN];
__device__ int   g_col[NE];
__device__ float g_agg[(size_t)NN * DH];
__device__ float g_h1[(size_t)NN * DH];
__device__ float g_h2[(size_t)NN * DH];

// ---------------- graph build ----------------
__global__ void k_zero() {
    int i = blockIdx.x * blockDim.x + threadIdx.x;
    if (i < NN) { g_deg[i] = 0; g_cur[i] = 0; }
}

__global__ void k_count(const int* __restrict__ dst) {
    int e = blockIdx.x * blockDim.x + threadIdx.x;
    if (e < NE) atomicAdd(&g_deg[dst[e]], 1);
}

// single-block exclusive scan over 100k degrees (1024 threads, chunked)
__global__ void k_scan() {
    __shared__ int wsum[32];
    __shared__ int s_total;
    int tid = threadIdx.x, lane = tid & 31, wid = tid >> 5;
    int carry = 0;
    for (int base = 0; base < NN; base += 1024) {
        int i = base + tid;
        int v = (i < NN) ? g_deg[i] : 0;
        int x = v;
#pragma unroll
        for (int o = 1; o < 32; o <<= 1) {
            int y = __shfl_up_sync(0xffffffffu, x, o);
            if (lane >= o) x += y;
        }
        if (lane == 31) wsum[wid] = x;
        __syncthreads();
        if (tid == 0) {
            int acc = 0;
#pragma unroll
            for (int w = 0; w < 32; w++) { int t = wsum[w]; wsum[w] = acc; acc += t; }
            s_total = acc;
        }
        __syncthreads();
        if (i < NN) {
            g_rp[i]  = carry + wsum[wid] + x - v;   // exclusive prefix
            g_inv[i] = 1.0f / (float)(v > 1 ? v : 1);
        }
        carry += s_total;
        __syncthreads();
    }
    if (tid == 0) g_rp[NN] = carry;
}

__global__ void k_fill(const int* __restrict__ src, const int* __restrict__ dst) {
    int e = blockIdx.x * blockDim.x + threadIdx.x;
    if (e < NE) {
        int d = dst[e];
        int p = atomicAdd(&g_cur[d], 1);
        g_col[g_rp[d] + p] = src[e];
    }
}

// ---------------- mean aggregation: one warp per node, float4 lanes ----------------
__global__ void k_agg(const float* __restrict__ x, float* __restrict__ out) {
    int gw = (blockIdx.x * blockDim.x + threadIdx.x) >> 5;
    if (gw >= NN) return;
    int lane = threadIdx.x & 31;
    int s = g_rp[gw], e = g_rp[gw + 1];
    const float4* xv = (const float4*)x;
    float4 acc = make_float4(0.f, 0.f, 0.f, 0.f);
    int j = s;
    for (; j + 4 <= e; j += 4) {
        int n0 = g_col[j], n1 = g_col[j + 1], n2 = g_col[j + 2], n3 = g_col[j + 3];
        float4 v0 = xv[n0 * 32 + lane];
        float4 v1 = xv[n1 * 32 + lane];
        float4 v2 = xv[n2 * 32 + lane];
        float4 v3 = xv[n3 * 32 + lane];
        acc.x += (v0.x + v1.x) + (v2.x + v3.x);
        acc.y += (v0.y + v1.y) + (v2.y + v3.y);
        acc.z += (v0.z + v1.z) + (v2.z + v3.z);
        acc.w += (v0.w + v1.w) + (v2.w + v3.w);
    }
    for (; j < e; j++) {
        int n0 = g_col[j];
        float4 v0 = xv[n0 * 32 + lane];
        acc.x += v0.x; acc.y += v0.y; acc.z += v0.z; acc.w += v0.w;
    }
    float id = g_inv[gw];
    acc.x *= id; acc.y *= id; acc.z *= id; acc.w *= id;
    ((float4*)out)[gw * 32 + lane] = acc;
}

// ---------------- Y[M,128] = relu(A[M,128] @ W^T + b),  W[128,128] ----------------
// block: 256 thr, 64-row tile; thread: 4 rows x 8 cols
__global__ void k_gemm128(const float* __restrict__ A, const float* __restrict__ W,
                          const float* __restrict__ bias, float* __restrict__ Y) {
    extern __shared__ float sm[];
    float* Ws = sm;               // [128 k][132 pad] : Ws[k*132+o] = W[o][k]
    float* As = sm + 128 * 132;   // [64 r][132 pad]
    int tid = threadIdx.x;
    int row0 = blockIdx.x * 64;

    for (int idx = tid; idx < 128 * 128; idx += 256) {
        int o = idx >> 7, k = idx & 127;
        Ws[k * 132 + o] = W[idx];
    }
    for (int idx = tid; idx < 64 * 128; idx += 256) {
        int r = idx >> 7, k = idx & 127;
        int gr = row0 + r;
        As[r * 132 + k] = (gr < NN) ? A[(size_t)gr * 128 + k] : 0.f;
    }
    __syncthreads();

    int tc = tid & 15, tr = tid >> 4;   // cols tc*8..+7, rows tr*4..+3
    float acc[4][8];
#pragma unroll
    for (int r = 0; r < 4; r++)
#pragma unroll
        for (int c = 0; c < 8; c++) acc[r][c] = 0.f;

#pragma unroll 8
    for (int k = 0; k < 128; k++) {
        float a[4];
#pragma unroll
        for (int r = 0; r < 4; r++) a[r] = As[(tr * 4 + r) * 132 + k];
        float4 b0 = *(const float4*)&Ws[k * 132 + tc * 8];
        float4 b1 = *(const float4*)&Ws[k * 132 + tc * 8 + 4];
        float b[8] = {b0.x, b0.y, b0.z, b0.w, b1.x, b1.y, b1.z, b1.w};
#pragma unroll
        for (int r = 0; r < 4; r++)
#pragma unroll
            for (int c = 0; c < 8; c++) acc[r][c] += a[r] * b[c];
    }

    float bv[8];
#pragma unroll
    for (int c = 0; c < 8; c++) bv[c] = bias[tc * 8 + c];
#pragma unroll
    for (int r = 0; r < 4; r++) {
        int gr = row0 + tr * 4 + r;
        if (gr < NN) {
            float4 o0, o1;
            o0.x = fmaxf(acc[r][0] + bv[0], 0.f);
            o0.y = fmaxf(acc[r][1] + bv[1], 0.f);
            o0.z = fmaxf(acc[r][2] + bv[2], 0.f);
            o0.w = fmaxf(acc[r][3] + bv[3], 0.f);
            o1.x = fmaxf(acc[r][4] + bv[4], 0.f);
            o1.y = fmaxf(acc[r][5] + bv[5], 0.f);
            o1.z = fmaxf(acc[r][6] + bv[6], 0.f);
            o1.w = fmaxf(acc[r][7] + bv[7], 0.f);
            *(float4*)&Y[(size_t)gr * 128 + tc * 8]     = o0;
            *(float4*)&Y[(size_t)gr * 128 + tc * 8 + 4] = o1;
        }
    }
}

// ---------------- logits + log_softmax: [h1|h2] @ Wl^T + bl ----------------
// block: 128 thr, 64-row x 64-col tile; thread: 4 rows x 8 cols; K=256 in 2 phases
__global__ void k_logits(const float* __restrict__ Wl, const float* __restrict__ bl,
                         float* __restrict__ out) {
    extern __shared__ float sm[];
    float* Ws = sm;              // [128 k][68 pad]
    float* As = sm + 128 * 68;   // [64 r][132 pad]
    int tid = threadIdx.x;
    int row0 = blockIdx.x * 64;
    int tc = tid & 7, tr = tid >> 3;    // cols tc*8..+7, rows tr*4..+3

    float acc[4][8];
#pragma unroll
    for (int r = 0; r < 4; r++)
#pragma unroll
        for (int c = 0; c < 8; c++) acc[r][c] = 0.f;

    for (int kt = 0; kt < 2; kt++) {
        const float* X = kt ? g_h2 : g_h1;
        __syncthreads();
        for (int idx = tid; idx < 64 * 128; idx += 128) {
            int r = idx >> 7, k = idx & 127;
            int gr = row0 + r;
            As[r * 132 + k] = (gr < NN) ? X[(size_t)gr * 128 + k] : 0.f;
        }
        for (int idx = tid; idx < 64 * 128; idx += 128) {
            int c = idx >> 7, k = idx & 127;
            Ws[k * 68 + c] = Wl[c * 256 + kt * 128 + k];
        }
        __syncthreads();

#pragma unroll 8
        for (int k = 0; k < 128; k++) {
            float a[4];
#pragma unroll
            for (int r = 0; r < 4; r++) a[r] = As[(tr * 4 + r) * 132 + k];
            float4 b0 = *(const float4*)&Ws[k * 68 + tc * 8];
            float4 b1 = *(const float4*)&Ws[k * 68 + tc * 8 + 4];
            float b[8] = {b0.x, b0.y, b0.z, b0.w, b1.x, b1.y, b1.z, b1.w};
#pragma unroll
            for (int r = 0; r < 4; r++)
#pragma unroll
                for (int c = 0; c < 8; c++) acc[r][c] += a[r] * b[c];
        }
    }

    float bv[8];
#pragma unroll
    for (int c = 0; c < 8; c++) bv[c] = bl[tc * 8 + c];

    // log_softmax per row; each row owned by 8 consecutive lanes (shfl_xor 1,2,4)
#pragma unroll
    for (int r = 0; r < 4; r++) {
        float m = -1e30f;
#pragma unroll
        for (int c = 0; c < 8; c++) { acc[r][c] += bv[c]; m = fmaxf(m, acc[r][c]); }
        m = fmaxf(m, __shfl_xor_sync(0xffffffffu, m, 1));
        m = fmaxf(m, __shfl_xor_sync(0xffffffffu, m, 2));
        m = fmaxf(m, __shfl_xor_sync(0xffffffffu, m, 4));
        float s = 0.f;
#pragma unroll
        for (int c = 0; c < 8; c++) s += expf(acc[r][c] - m);
        s += __shfl_xor_sync(0xffffffffu, s, 1);
        s += __shfl_xor_sync(0xffffffffu, s, 2);
        s += __shfl_xor_sync(0xffffffffu, s, 4);
        float lse = m + logf(s);
        int gr = row0 + tr * 4 + r;
        if (gr < NN) {
            float4 o0, o1;
            o0.x = acc[r][0] - lse; o0.y = acc[r][1] - lse;
            o0.z = acc[r][2] - lse; o0.w = acc[r][3] - lse;
            o1.x = acc[r][4] - lse; o1.y = acc[r][5] - lse;
            o1.z = acc[r][6] - lse; o1.w = acc[r][7] - lse;
            *(float4*)&out[(size_t)gr * 64 + tc * 8]     = o0;
            *(float4*)&out[(size_t)gr * 64 + tc * 8 + 4] = o1;
        }
    }
}

extern "C" void kernel_launch(void* const* d_in, const int* in_sizes, int n_in,
                              void* d_out, int out_size) {
    const float* feat = (const float*)d_in[0];
    const int*   src  = (const int*)d_in[1];
    const int*   dst  = (const int*)d_in[2];
    const float* W1   = (const float*)d_in[3];
    const float* b1   = (const float*)d_in[4];
    const float* W2   = (const float*)d_in[5];
    const float* b2   = (const float*)d_in[6];
    const float* Wl   = (const float*)d_in[7];
    const float* bl   = (const float*)d_in[8];
    float* out = (float*)d_out;

    void *p_agg, *p_h1, *p_h2;
    cudaGetSymbolAddress(&p_agg, g_agg);
    cudaGetSymbolAddress(&p_h1,  g_h1);
    cudaGetSymbolAddress(&p_h2,  g_h2);

    const int SMEM_GEMM   = (128 * 132 + 64 * 132) * 4;  // 101376
    const int SMEM_LOGITS = (128 * 68  + 64 * 132) * 4;  // 68608
    cudaFuncSetAttribute(k_gemm128, cudaFuncAttributeMaxDynamicSharedMemorySize, SMEM_GEMM);
    cudaFuncSetAttribute(k_logits,  cudaFuncAttributeMaxDynamicSharedMemorySize, SMEM_LOGITS);

    // graph build (per-launch, deterministic work)
    k_zero <<<(NN + 255) / 256, 256>>>();
    k_count<<<(NE + 255) / 256, 256>>>(dst);
    k_scan <<<1, 1024>>>();
    k_fill <<<(NE + 255) / 256, 256>>>(src, dst);

    // layer 1
    k_agg<<<(NN * 32 + 255) / 256, 256>>>(feat, (float*)p_agg);
    k_gemm128<<<(NN + 63) / 64, 256, SMEM_GEMM>>>((const float*)p_agg, W1, b1, (float*)p_h1);

    // layer 2
    k_agg<<<(NN * 32 + 255) / 256, 256>>>((const float*)p_h1, (float*)p_agg);
    k_gemm128<<<(NN + 63) / 64, 256, SMEM_GEMM>>>((const float*)p_agg, W2, b2, (float*)p_h2);

    // logits + log_softmax
    k_logits<<<(NN + 63) / 64, 128, SMEM_LOGITS>>>(Wl, bl, out);
}

// round 6
// speedup vs baseline: 2.6460x; 2.6460x over previous
#include <cuda_runtime.h>
#include <math.h>
#include <stdint.h>

#define NN 100000
#define NE 1600000
#define DH 128
#define NC 64

// ---- persistent scratch (no allocations allowed) ----
__device__ int   g_deg[NN];
__device__ float g_inv[NN];
__device__ int   g_rp[NN + 1];
__device__ int   g_cur[NN];
__device__ int   g_col[NE];
__device__ float g_agg[(size_t)NN * DH];
__device__ float g_h1[(size_t)NN * DH];
__device__ float g_h2[(size_t)NN * DH];

// ---------------- tf32 warp-MMA helpers ----------------
__device__ __forceinline__ uint32_t tf32_of(float f) {
    uint32_t r;
    asm("cvt.rna.tf32.f32 %0, %1;" : "=r"(r) : "f"(f));
    return r;
}
__device__ __forceinline__ void mma_tf32(float (&c)[4], const uint32_t (&a)[4],
                                         const uint32_t (&b)[2]) {
    asm volatile(
        "mma.sync.aligned.m16n8k8.row.col.f32.tf32.tf32.f32 "
        "{%0,%1,%2,%3}, {%4,%5,%6,%7}, {%8,%9}, {%0,%1,%2,%3};"
        : "+f"(c[0]), "+f"(c[1]), "+f"(c[2]), "+f"(c[3])
        : "r"(a[0]), "r"(a[1]), "r"(a[2]), "r"(a[3]), "r"(b[0]), "r"(b[1]));
}

// ---------------- graph build ----------------
__global__ void k_zero() {
    int i = blockIdx.x * blockDim.x + threadIdx.x;
    if (i < NN) { g_deg[i] = 0; g_cur[i] = 0; }
}

__global__ void k_count(const int* __restrict__ dst) {
    int e = blockIdx.x * blockDim.x + threadIdx.x;
    if (e < NE) atomicAdd(&g_deg[dst[e]], 1);
}

// single-block exclusive scan over 100k degrees (1024 threads, chunked)
__global__ void k_scan() {
    __shared__ int wsum[32];
    __shared__ int s_total;
    int tid = threadIdx.x, lane = tid & 31, wid = tid >> 5;
    int carry = 0;
    for (int base = 0; base < NN; base += 1024) {
        int i = base + tid;
        int v = (i < NN) ? g_deg[i] : 0;
        int x = v;
#pragma unroll
        for (int o = 1; o < 32; o <<= 1) {
            int y = __shfl_up_sync(0xffffffffu, x, o);
            if (lane >= o) x += y;
        }
        if (lane == 31) wsum[wid] = x;
        __syncthreads();
        if (tid == 0) {
            int acc = 0;
#pragma unroll
            for (int w = 0; w < 32; w++) { int t = wsum[w]; wsum[w] = acc; acc += t; }
            s_total = acc;
        }
        __syncthreads();
        if (i < NN) {
            g_rp[i]  = carry + wsum[wid] + x - v;   // exclusive prefix
            g_inv[i] = 1.0f / (float)(v > 1 ? v : 1);
        }
        carry += s_total;
        __syncthreads();
    }
    if (tid == 0) g_rp[NN] = carry;
}

__global__ void k_fill(const int* __restrict__ src, const int* __restrict__ dst) {
    int e = blockIdx.x * blockDim.x + threadIdx.x;
    if (e < NE) {
        int d = dst[e];
        int p = atomicAdd(&g_cur[d], 1);
        g_col[g_rp[d] + p] = src[e];
    }
}

// ---------------- mean aggregation: one warp per node, float4 lanes ----------------
__global__ void k_agg(const float* __restrict__ x, float* __restrict__ out) {
    int gw = (blockIdx.x * blockDim.x + threadIdx.x) >> 5;
    if (gw >= NN) return;
    int lane = threadIdx.x & 31;
    int s = g_rp[gw], e = g_rp[gw + 1];
    const float4* xv = (const float4*)x;
    float4 acc = make_float4(0.f, 0.f, 0.f, 0.f);
    int j = s;
    for (; j + 4 <= e; j += 4) {
        int n0 = g_col[j], n1 = g_col[j + 1], n2 = g_col[j + 2], n3 = g_col[j + 3];
        float4 v0 = xv[n0 * 32 + lane];
        float4 v1 = xv[n1 * 32 + lane];
        float4 v2 = xv[n2 * 32 + lane];
        float4 v3 = xv[n3 * 32 + lane];
        acc.x += (v0.x + v1.x) + (v2.x + v3.x);
        acc.y += (v0.y + v1.y) + (v2.y + v3.y);
        acc.z += (v0.z + v1.z) + (v2.z + v3.z);
        acc.w += (v0.w + v1.w) + (v2.w + v3.w);
    }
    for (; j < e; j++) {
        int n0 = g_col[j];
        float4 v0 = xv[n0 * 32 + lane];
        acc.x += v0.x; acc.y += v0.y; acc.z += v0.z; acc.w += v0.w;
    }
    float id = g_inv[gw];
    acc.x *= id; acc.y *= id; acc.z *= id; acc.w *= id;
    ((float4*)out)[gw * 32 + lane] = acc;
}

// ---------------- Y[M,128] = relu(A[M,128] @ W^T + b) via tf32 warp-MMA ----------------
// block 256 thr (8 warps), tile M=64, N=128, K=128
__global__ void k_gemm128(const float* __restrict__ A, const float* __restrict__ W,
                          const float* __restrict__ bias, float* __restrict__ Y) {
    extern __shared__ float sm[];
    float* As = sm;               // [64][132]
    float* Bs = sm + 64 * 132;    // [128][132] : Bs[n][k] = W[n][k]
    int tid = threadIdx.x;
    int row0 = blockIdx.x * 64;

    const float4* W4 = (const float4*)W;
    for (int idx = tid; idx < 128 * 32; idx += 256) {
        int n = idx >> 5, kq = idx & 31;
        float4 v = W4[idx];
        *(float4*)&Bs[n * 132 + kq * 4] = v;
    }
    const float4* A4 = (const float4*)A;
    for (int idx = tid; idx < 64 * 32; idx += 256) {
        int r = idx >> 5, kq = idx & 31;
        int gr = row0 + r;
        float4 v = (gr < NN) ? A4[(size_t)gr * 32 + kq] : make_float4(0.f, 0.f, 0.f, 0.f);
        *(float4*)&As[r * 132 + kq * 4] = v;
    }
    __syncthreads();

    int warp = tid >> 5, lane = tid & 31;
    int warpM = warp & 1;         // 2 -> 32 rows each
    int warpN = warp >> 1;        // 4 -> 32 cols each
    int g = lane >> 2, tg = lane & 3;

    float acc[2][4][4];
#pragma unroll
    for (int t = 0; t < 2; t++)
#pragma unroll
        for (int j = 0; j < 4; j++)
#pragma unroll
            for (int q = 0; q < 4; q++) acc[t][j][q] = 0.f;

#pragma unroll
    for (int k0 = 0; k0 < 128; k0 += 8) {
        uint32_t a[2][4], b[4][2];
#pragma unroll
        for (int t = 0; t < 2; t++) {
            int r = warpM * 32 + t * 16 + g;
            a[t][0] = tf32_of(As[r * 132 + k0 + tg]);
            a[t][1] = tf32_of(As[(r + 8) * 132 + k0 + tg]);
            a[t][2] = tf32_of(As[r * 132 + k0 + tg + 4]);
            a[t][3] = tf32_of(As[(r + 8) * 132 + k0 + tg + 4]);
        }
#pragma unroll
        for (int j = 0; j < 4; j++) {
            int n = warpN * 32 + j * 8 + g;
            b[j][0] = tf32_of(Bs[n * 132 + k0 + tg]);
            b[j][1] = tf32_of(Bs[n * 132 + k0 + tg + 4]);
        }
#pragma unroll
        for (int t = 0; t < 2; t++)
#pragma unroll
            for (int j = 0; j < 4; j++) mma_tf32(acc[t][j], a[t], b[j]);
    }

#pragma unroll
    for (int t = 0; t < 2; t++) {
        int r = row0 + warpM * 32 + t * 16 + g;
#pragma unroll
        for (int j = 0; j < 4; j++) {
            int c = warpN * 32 + j * 8 + tg * 2;
            float bc0 = bias[c], bc1 = bias[c + 1];
            if (r < NN) {
                float2 o;
                o.x = fmaxf(acc[t][j][0] + bc0, 0.f);
                o.y = fmaxf(acc[t][j][1] + bc1, 0.f);
                *(float2*)&Y[(size_t)r * 128 + c] = o;
            }
            if (r + 8 < NN) {
                float2 o;
                o.x = fmaxf(acc[t][j][2] + bc0, 0.f);
                o.y = fmaxf(acc[t][j][3] + bc1, 0.f);
                *(float2*)&Y[(size_t)(r + 8) * 128 + c] = o;
            }
        }
    }
}

// ---------------- logits + log_softmax via tf32 warp-MMA ----------------
// block 256 thr (8 warps), tile M=128, N=64, K=256 (two 128 phases: h1 then h2)
__global__ void k_logits(const float* __restrict__ Wl, const float* __restrict__ bl,
                         float* __restrict__ out) {
    extern __shared__ float sm[];
    float* As = sm;               // [128][132]
    float* Ws = sm + 128 * 132;   // [64][132]
    int tid = threadIdx.x;
    int row0 = blockIdx.x * 128;
    int warp = tid >> 5, lane = tid & 31;
    int warpM = warp & 3;         // 4 -> 32 rows each
    int warpN = warp >> 2;        // 2 -> 32 cols each
    int g = lane >> 2, tg = lane & 3;

    float acc[2][4][4];
#pragma unroll
    for (int t = 0; t < 2; t++)
#pragma unroll
        for (int j = 0; j < 4; j++)
#pragma unroll
            for (int q = 0; q < 4; q++) acc[t][j][q] = 0.f;

    const float4* Wl4 = (const float4*)Wl;
    for (int ph = 0; ph < 2; ph++) {
        const float* X = ph ? g_h2 : g_h1;
        const float4* X4 = (const float4*)X;
        __syncthreads();
        for (int idx = tid; idx < 128 * 32; idx += 256) {
            int r = idx >> 5, kq = idx & 31;
            int gr = row0 + r;
            float4 v = (gr < NN) ? X4[(size_t)gr * 32 + kq] : make_float4(0.f, 0.f, 0.f, 0.f);
            *(float4*)&As[r * 132 + kq * 4] = v;
        }
        for (int idx = tid; idx < 64 * 32; idx += 256) {
            int n = idx >> 5, kq = idx & 31;
            float4 v = Wl4[n * 64 + ph * 32 + kq];
            *(float4*)&Ws[n * 132 + kq * 4] = v;
        }
        __syncthreads();

#pragma unroll
        for (int k0 = 0; k0 < 128; k0 += 8) {
            uint32_t a[2][4], b[4][2];
#pragma unroll
            for (int t = 0; t < 2; t++) {
                int r = warpM * 32 + t * 16 + g;
                a[t][0] = tf32_of(As[r * 132 + k0 + tg]);
                a[t][1] = tf32_of(As[(r + 8) * 132 + k0 + tg]);
                a[t][2] = tf32_of(As[r * 132 + k0 + tg + 4]);
                a[t][3] = tf32_of(As[(r + 8) * 132 + k0 + tg + 4]);
            }
#pragma unroll
            for (int j = 0; j < 4; j++) {
                int n = warpN * 32 + j * 8 + g;
                b[j][0] = tf32_of(Ws[n * 132 + k0 + tg]);
                b[j][1] = tf32_of(Ws[n * 132 + k0 + tg + 4]);
            }
#pragma unroll
            for (int t = 0; t < 2; t++)
#pragma unroll
                for (int j = 0; j < 4; j++) mma_tf32(acc[t][j], a[t], b[j]);
        }
    }

    // stage logits (+bias) into smem [128][68], then per-row log_softmax
    __syncthreads();
    float* Ls = sm;  // reuse As region: 128*68 floats fit well inside allocation
#pragma unroll
    for (int t = 0; t < 2; t++) {
        int r = warpM * 32 + t * 16 + g;
#pragma unroll
        for (int j = 0; j < 4; j++) {
            int c = warpN * 32 + j * 8 + tg * 2;
            float bc0 = bl[c], bc1 = bl[c + 1];
            Ls[r * 68 + c]           = acc[t][j][0] + bc0;
            Ls[r * 68 + c + 1]       = acc[t][j][1] + bc1;
            Ls[(r + 8) * 68 + c]     = acc[t][j][2] + bc0;
            Ls[(r + 8) * 68 + c + 1] = acc[t][j][3] + bc1;
        }
    }
    __syncthreads();

    // each warp owns 16 rows
    for (int rr = warp * 16; rr < warp * 16 + 16; rr++) {
        float v0 = Ls[rr * 68 + lane];
        float v1 = Ls[rr * 68 + 32 + lane];
        float m = fmaxf(v0, v1);
#pragma unroll
        for (int o = 16; o > 0; o >>= 1) m = fmaxf(m, __shfl_xor_sync(0xffffffffu, m, o));
        float s = expf(v0 - m) + expf(v1 - m);
#pragma unroll
        for (int o = 16; o > 0; o >>= 1) s += __shfl_xor_sync(0xffffffffu, s, o);
        float lse = m + logf(s);
        int gr = row0 + rr;
        if (gr < NN) {
            out[(size_t)gr * 64 + lane]      = v0 - lse;
            out[(size_t)gr * 64 + 32 + lane] = v1 - lse;
        }
    }
}

extern "C" void kernel_launch(void* const* d_in, const int* in_sizes, int n_in,
                              void* d_out, int out_size) {
    const float* feat = (const float*)d_in[0];
    const int*   src  = (const int*)d_in[1];
    const int*   dst  = (const int*)d_in[2];
    const float* W1   = (const float*)d_in[3];
    const float* b1   = (const float*)d_in[4];
    const float* W2   = (const float*)d_in[5];
    const float* b2   = (const float*)d_in[6];
    const float* Wl   = (const float*)d_in[7];
    const float* bl   = (const float*)d_in[8];
    float* out = (float*)d_out;

    void *p_agg, *p_h1, *p_h2;
    cudaGetSymbolAddress(&p_agg, g_agg);
    cudaGetSymbolAddress(&p_h1,  g_h1);
    cudaGetSymbolAddress(&p_h2,  g_h2);

    const int SMEM_GEMM   = (64 * 132 + 128 * 132) * 4;   // 101376
    const int SMEM_LOGITS = (128 * 132 + 64 * 132) * 4;   // 101376
    cudaFuncSetAttribute(k_gemm128, cudaFuncAttributeMaxDynamicSharedMemorySize, SMEM_GEMM);
    cudaFuncSetAttribute(k_logits,  cudaFuncAttributeMaxDynamicSharedMemorySize, SMEM_LOGITS);

    // graph build (per-launch, deterministic work)
    k_zero <<<(NN + 255) / 256, 256>>>();
    k_count<<<(NE + 255) / 256, 256>>>(dst);
    k_scan <<<1, 1024>>>();
    k_fill <<<(NE + 255) / 256, 256>>>(src, dst);

    // layer 1
    k_agg<<<(NN * 32 + 255) / 256, 256>>>(feat, (float*)p_agg);
    k_gemm128<<<(NN + 63) / 64, 256, SMEM_GEMM>>>((const float*)p_agg, W1, b1, (float*)p_h1);

    // layer 2
    k_agg<<<(NN * 32 + 255) / 256, 256>>>((const float*)p_h1, (float*)p_agg);
    k_gemm128<<<(NN + 63) / 64, 256, SMEM_GEMM>>>((const float*)p_agg, W2, b2, (float*)p_h2);

    // logits + log_softmax
    k_logits<<<(NN + 127) / 128, 256, SMEM_LOGITS>>>(Wl, bl, out);
}

// round 7
// speedup vs baseline: 2.6552x; 1.0035x over previous
#include <cuda_runtime.h>
#include <cuda_bf16.h>
#include <math.h>
#include <stdint.h>

#define NN 100000
#define NE 1600000
#define DH 128
#define NC 64

// ---- persistent scratch (no allocations allowed) ----
__device__ int   g_deg[NN];
__device__ float g_inv[NN];
__device__ int   g_rp[NN + 1];
__device__ int   g_cur[NN];
__device__ int   g_col[NE];
__device__ float g_agg[(size_t)NN * DH];
__device__ float g_h1[(size_t)NN * DH];
__device__ float g_h2[(size_t)NN * DH];
__device__ __nv_bfloat16 g_featb[(size_t)NN * DH];
__device__ __nv_bfloat16 g_h1b[(size_t)NN * DH];

// ---------------- tf32 warp-MMA helpers ----------------
__device__ __forceinline__ uint32_t tf32_of(float f) {
    uint32_t r;
    asm("cvt.rna.tf32.f32 %0, %1;" : "=r"(r) : "f"(f));
    return r;
}
__device__ __forceinline__ void mma_tf32(float (&c)[4], const uint32_t (&a)[4],
                                         const uint32_t (&b)[2]) {
    asm volatile(
        "mma.sync.aligned.m16n8k8.row.col.f32.tf32.tf32.f32 "
        "{%0,%1,%2,%3}, {%4,%5,%6,%7}, {%8,%9}, {%0,%1,%2,%3};"
        : "+f"(c[0]), "+f"(c[1]), "+f"(c[2]), "+f"(c[3])
        : "r"(a[0]), "r"(a[1]), "r"(a[2]), "r"(a[3]), "r"(b[0]), "r"(b[1]));
}

// ---------------- graph build ----------------
__global__ void k_zero() {
    int i = blockIdx.x * blockDim.x + threadIdx.x;
    if (i < NN) { g_deg[i] = 0; g_cur[i] = 0; }
}

__global__ void k_count(const int* __restrict__ dst) {
    int e = blockIdx.x * blockDim.x + threadIdx.x;
    if (e < NE) atomicAdd(&g_deg[dst[e]], 1);
}

// single-block exclusive scan over 100k degrees (1024 threads, chunked)
__global__ void k_scan() {
    __shared__ int wsum[32];
    __shared__ int s_total;
    int tid = threadIdx.x, lane = tid & 31, wid = tid >> 5;
    int carry = 0;
    for (int base = 0; base < NN; base += 1024) {
        int i = base + tid;
        int v = (i < NN) ? g_deg[i] : 0;
        int x = v;
#pragma unroll
        for (int o = 1; o < 32; o <<= 1) {
            int y = __shfl_up_sync(0xffffffffu, x, o);
            if (lane >= o) x += y;
        }
        if (lane == 31) wsum[wid] = x;
        __syncthreads();
        if (tid == 0) {
            int acc = 0;
#pragma unroll
            for (int w = 0; w < 32; w++) { int t = wsum[w]; wsum[w] = acc; acc += t; }
            s_total = acc;
        }
        __syncthreads();
        if (i < NN) {
            g_rp[i]  = carry + wsum[wid] + x - v;   // exclusive prefix
            g_inv[i] = 1.0f / (float)(v > 1 ? v : 1);
        }
        carry += s_total;
        __syncthreads();
    }
    if (tid == 0) g_rp[NN] = carry;
}

__global__ void k_fill(const int* __restrict__ src, const int* __restrict__ dst) {
    int e = blockIdx.x * blockDim.x + threadIdx.x;
    if (e < NE) {
        int d = dst[e];
        int p = atomicAdd(&g_cur[d], 1);
        g_col[g_rp[d] + p] = src[e];
    }
}

// ---------------- fp32 -> bf16 conversion ----------------
__global__ void k_tobf16(const float4* __restrict__ x, __nv_bfloat162* __restrict__ y) {
    int i = blockIdx.x * blockDim.x + threadIdx.x;
    if (i < NN * DH / 4) {
        float4 v = x[i];
        y[2 * i]     = __floats2bfloat162_rn(v.x, v.y);
        y[2 * i + 1] = __floats2bfloat162_rn(v.z, v.w);
    }
}

// ---------------- mean aggregation from bf16: one warp per node ----------------
// lane owns features [lane*4, lane*4+4) : one uint2 (4 bf16) per neighbor row
__global__ void k_agg_bf(const __nv_bfloat16* __restrict__ xb, float* __restrict__ out) {
    int gw = (blockIdx.x * blockDim.x + threadIdx.x) >> 5;
    if (gw >= NN) return;
    int lane = threadIdx.x & 31;
    int s = g_rp[gw], e = g_rp[gw + 1];
    const uint2* xv = (const uint2*)xb;   // row = 32 uint2
    float4 acc = make_float4(0.f, 0.f, 0.f, 0.f);
    int j = s;
    for (; j + 4 <= e; j += 4) {
        int n0 = g_col[j], n1 = g_col[j + 1], n2 = g_col[j + 2], n3 = g_col[j + 3];
        uint2 u0 = xv[n0 * 32 + lane];
        uint2 u1 = xv[n1 * 32 + lane];
        uint2 u2 = xv[n2 * 32 + lane];
        uint2 u3 = xv[n3 * 32 + lane];
#pragma unroll
        for (int q = 0; q < 4; q++) {
            uint2 u = q == 0 ? u0 : q == 1 ? u1 : q == 2 ? u2 : u3;
            float2 lo = __bfloat1622float2(*(__nv_bfloat162*)&u.x);
            float2 hi = __bfloat1622float2(*(__nv_bfloat162*)&u.y);
            acc.x += lo.x; acc.y += lo.y; acc.z += hi.x; acc.w += hi.y;
        }
    }
    for (; j < e; j++) {
        uint2 u = xv[g_col[j] * 32 + lane];
        float2 lo = __bfloat1622float2(*(__nv_bfloat162*)&u.x);
        float2 hi = __bfloat1622float2(*(__nv_bfloat162*)&u.y);
        acc.x += lo.x; acc.y += lo.y; acc.z += hi.x; acc.w += hi.y;
    }
    float id = g_inv[gw];
    acc.x *= id; acc.y *= id; acc.z *= id; acc.w *= id;
    ((float4*)out)[gw * 32 + lane] = acc;
}

// ---------------- Y[M,128] = relu(A[M,128] @ W^T + b) via tf32 warp-MMA ----------------
// block 256 thr (8 warps), tile M=64, N=128, K=128; optional bf16 dual write
__global__ void k_gemm128(const float* __restrict__ A, const float* __restrict__ W,
                          const float* __restrict__ bias, float* __restrict__ Y,
                          __nv_bfloat16* __restrict__ Yb) {
    extern __shared__ float sm[];
    float* As = sm;               // [64][132]
    float* Bs = sm + 64 * 132;    // [128][132] : Bs[n][k] = W[n][k]
    int tid = threadIdx.x;
    int row0 = blockIdx.x * 64;

    const float4* W4 = (const float4*)W;
    for (int idx = tid; idx < 128 * 32; idx += 256) {
        int n = idx >> 5, kq = idx & 31;
        float4 v = W4[idx];
        *(float4*)&Bs[n * 132 + kq * 4] = v;
    }
    const float4* A4 = (const float4*)A;
    for (int idx = tid; idx < 64 * 32; idx += 256) {
        int r = idx >> 5, kq = idx & 31;
        int gr = row0 + r;
        float4 v = (gr < NN) ? A4[(size_t)gr * 32 + kq] : make_float4(0.f, 0.f, 0.f, 0.f);
        *(float4*)&As[r * 132 + kq * 4] = v;
    }
    __syncthreads();

    int warp = tid >> 5, lane = tid & 31;
    int warpM = warp & 1;         // 2 -> 32 rows each
    int warpN = warp >> 1;        // 4 -> 32 cols each
    int g = lane >> 2, tg = lane & 3;

    float acc[2][4][4];
#pragma unroll
    for (int t = 0; t < 2; t++)
#pragma unroll
        for (int j = 0; j < 4; j++)
#pragma unroll
            for (int q = 0; q < 4; q++) acc[t][j][q] = 0.f;

#pragma unroll
    for (int k0 = 0; k0 < 128; k0 += 8) {
        uint32_t a[2][4], b[4][2];
#pragma unroll
        for (int t = 0; t < 2; t++) {
            int r = warpM * 32 + t * 16 + g;
            a[t][0] = tf32_of(As[r * 132 + k0 + tg]);
            a[t][1] = tf32_of(As[(r + 8) * 132 + k0 + tg]);
            a[t][2] = tf32_of(As[r * 132 + k0 + tg + 4]);
            a[t][3] = tf32_of(As[(r + 8) * 132 + k0 + tg + 4]);
        }
#pragma unroll
        for (int j = 0; j < 4; j++) {
            int n = warpN * 32 + j * 8 + g;
            b[j][0] = tf32_of(Bs[n * 132 + k0 + tg]);
            b[j][1] = tf32_of(Bs[n * 132 + k0 + tg + 4]);
        }
#pragma unroll
        for (int t = 0; t < 2; t++)
#pragma unroll
            for (int j = 0; j < 4; j++) mma_tf32(acc[t][j], a[t], b[j]);
    }

#pragma unroll
    for (int t = 0; t < 2; t++) {
        int r = row0 + warpM * 32 + t * 16 + g;
#pragma unroll
        for (int j = 0; j < 4; j++) {
            int c = warpN * 32 + j * 8 + tg * 2;
            float bc0 = bias[c], bc1 = bias[c + 1];
            if (r < NN) {
                float2 o;
                o.x = fmaxf(acc[t][j][0] + bc0, 0.f);
                o.y = fmaxf(acc[t][j][1] + bc1, 0.f);
                *(float2*)&Y[(size_t)r * 128 + c] = o;
                if (Yb) *(__nv_bfloat162*)&Yb[(size_t)r * 128 + c] = __floats2bfloat162_rn(o.x, o.y);
            }
            if (r + 8 < NN) {
                float2 o;
                o.x = fmaxf(acc[t][j][2] + bc0, 0.f);
                o.y = fmaxf(acc[t][j][3] + bc1, 0.f);
                *(float2*)&Y[(size_t)(r + 8) * 128 + c] = o;
                if (Yb) *(__nv_bfloat162*)&Yb[(size_t)(r + 8) * 128 + c] = __floats2bfloat162_rn(o.x, o.y);
            }
        }
    }
}

// ---------------- logits + log_softmax via tf32 warp-MMA ----------------
// block 256 thr (8 warps), tile M=128, N=64, K=256 (two 128 phases: h1 then h2)
__global__ void k_logits(const float* __restrict__ Wl, const float* __restrict__ bl,
                         float* __restrict__ out) {
    extern __shared__ float sm[];
    float* As = sm;               // [128][132]
    float* Ws = sm + 128 * 132;   // [64][132]
    int tid = threadIdx.x;
    int row0 = blockIdx.x * 128;
    int warp = tid >> 5, lane = tid & 31;
    int warpM = warp & 3;         // 4 -> 32 rows each
    int warpN = warp >> 2;        // 2 -> 32 cols each
    int g = lane >> 2, tg = lane & 3;

    float acc[2][4][4];
#pragma unroll
    for (int t = 0; t < 2; t++)
#pragma unroll
        for (int j = 0; j < 4; j++)
#pragma unroll
            for (int q = 0; q < 4; q++) acc[t][j][q] = 0.f;

    const float4* Wl4 = (const float4*)Wl;
    for (int ph = 0; ph < 2; ph++) {
        const float* X = ph ? g_h2 : g_h1;
        const float4* X4 = (const float4*)X;
        __syncthreads();
        for (int idx = tid; idx < 128 * 32; idx += 256) {
            int r = idx >> 5, kq = idx & 31;
            int gr = row0 + r;
            float4 v = (gr < NN) ? X4[(size_t)gr * 32 + kq] : make_float4(0.f, 0.f, 0.f, 0.f);
            *(float4*)&As[r * 132 + kq * 4] = v;
        }
        for (int idx = tid; idx < 64 * 32; idx += 256) {
            int n = idx >> 5, kq = idx & 31;
            float4 v = Wl4[n * 64 + ph * 32 + kq];
            *(float4*)&Ws[n * 132 + kq * 4] = v;
        }
        __syncthreads();

#pragma unroll
        for (int k0 = 0; k0 < 128; k0 += 8) {
            uint32_t a[2][4], b[4][2];
#pragma unroll
            for (int t = 0; t < 2; t++) {
                int r = warpM * 32 + t * 16 + g;
                a[t][0] = tf32_of(As[r * 132 + k0 + tg]);
                a[t][1] = tf32_of(As[(r + 8) * 132 + k0 + tg]);
                a[t][2] = tf32_of(As[r * 132 + k0 + tg + 4]);
                a[t][3] = tf32_of(As[(r + 8) * 132 + k0 + tg + 4]);
            }
#pragma unroll
            for (int j = 0; j < 4; j++) {
                int n = warpN * 32 + j * 8 + g;
                b[j][0] = tf32_of(Ws[n * 132 + k0 + tg]);
                b[j][1] = tf32_of(Ws[n * 132 + k0 + tg + 4]);
            }
#pragma unroll
            for (int t = 0; t < 2; t++)
#pragma unroll
                for (int j = 0; j < 4; j++) mma_tf32(acc[t][j], a[t], b[j]);
        }
    }

    // stage logits (+bias) into smem [128][68], then per-row log_softmax
    __syncthreads();
    float* Ls = sm;  // reuse As region
#pragma unroll
    for (int t = 0; t < 2; t++) {
        int r = warpM * 32 + t * 16 + g;
#pragma unroll
        for (int j = 0; j < 4; j++) {
            int c = warpN * 32 + j * 8 + tg * 2;
            float bc0 = bl[c], bc1 = bl[c + 1];
            Ls[r * 68 + c]           = acc[t][j][0] + bc0;
            Ls[r * 68 + c + 1]       = acc[t][j][1] + bc1;
            Ls[(r + 8) * 68 + c]     = acc[t][j][2] + bc0;
            Ls[(r + 8) * 68 + c + 1] = acc[t][j][3] + bc1;
        }
    }
    __syncthreads();

    // each warp owns 16 rows
    for (int rr = warp * 16; rr < warp * 16 + 16; rr++) {
        float v0 = Ls[rr * 68 + lane];
        float v1 = Ls[rr * 68 + 32 + lane];
        float m = fmaxf(v0, v1);
#pragma unroll
        for (int o = 16; o > 0; o >>= 1) m = fmaxf(m, __shfl_xor_sync(0xffffffffu, m, o));
        float s = expf(v0 - m) + expf(v1 - m);
#pragma unroll
        for (int o = 16; o > 0; o >>= 1) s += __shfl_xor_sync(0xffffffffu, s, o);
        float lse = m + logf(s);
        int gr = row0 + rr;
        if (gr < NN) {
            out[(size_t)gr * 64 + lane]      = v0 - lse;
            out[(size_t)gr * 64 + 32 + lane] = v1 - lse;
        }
    }
}

extern "C" void kernel_launch(void* const* d_in, const int* in_sizes, int n_in,
                              void* d_out, int out_size) {
    const float* feat = (const float*)d_in[0];
    const int*   src  = (const int*)d_in[1];
    const int*   dst  = (const int*)d_in[2];
    const float* W1   = (const float*)d_in[3];
    const float* b1   = (const float*)d_in[4];
    const float* W2   = (const float*)d_in[5];
    const float* b2   = (const float*)d_in[6];
    const float* Wl   = (const float*)d_in[7];
    const float* bl   = (const float*)d_in[8];
    float* out = (float*)d_out;

    void *p_agg, *p_h1, *p_h2, *p_fb, *p_h1b;
    cudaGetSymbolAddress(&p_agg, g_agg);
    cudaGetSymbolAddress(&p_h1,  g_h1);
    cudaGetSymbolAddress(&p_h2,  g_h2);
    cudaGetSymbolAddress(&p_fb,  g_featb);
    cudaGetSymbolAddress(&p_h1b, g_h1b);

    const int SMEM_GEMM   = (64 * 132 + 128 * 132) * 4;   // 101376
    const int SMEM_LOGITS = (128 * 132 + 64 * 132) * 4;   // 101376
    cudaFuncSetAttribute(k_gemm128, cudaFuncAttributeMaxDynamicSharedMemorySize, SMEM_GEMM);
    cudaFuncSetAttribute(k_logits,  cudaFuncAttributeMaxDynamicSharedMemorySize, SMEM_LOGITS);

    // graph build (per-launch, deterministic work)
    k_zero <<<(NN + 255) / 256, 256>>>();
    k_count<<<(NE + 255) / 256, 256>>>(dst);
    k_scan <<<1, 1024>>>();
    k_fill <<<(NE + 255) / 256, 256>>>(src, dst);

    // feat -> bf16 (independent of graph build order, but same stream is fine)
    k_tobf16<<<(NN * DH / 4 + 255) / 256, 256>>>((const float4*)feat, (__nv_bfloat162*)p_fb);

    // layer 1
    k_agg_bf<<<(NN * 32 + 255) / 256, 256>>>((const __nv_bfloat16*)p_fb, (float*)p_agg);
    k_gemm128<<<(NN + 63) / 64, 256, SMEM_GEMM>>>((const float*)p_agg, W1, b1,
                                                  (float*)p_h1, (__nv_bfloat16*)p_h1b);

    // layer 2
    k_agg_bf<<<(NN * 32 + 255) / 256, 256>>>((const __nv_bfloat16*)p_h1b, (float*)p_agg);
    k_gemm128<<<(NN + 63) / 64, 256, SMEM_GEMM>>>((const float*)p_agg, W2, b2,
                                                  (float*)p_h2, (__nv_bfloat16*)0);

    // logits + log_softmax
    k_logits<<<(NN + 127) / 128, 256, SMEM_LOGITS>>>(Wl, bl, out);
}

// round 10
// speedup vs baseline: 3.1974x; 1.2042x over previous
#include <cuda_runtime.h>
#include <cuda_bf16.h>
#include <math.h>
#include <stdint.h>

#define NN 100000
#define NE 1600000
#define DH 128
#define NC 64
#define SBLK 1024
#define NSB ((NN + SBLK - 1) / SBLK)   // 98

// ---- persistent scratch (no allocations allowed) ----
__device__ int   g_deg[NN];
__device__ float g_inv[NN];
__device__ int   g_rp[NN + 1];
__device__ int   g_cur[NN];
__device__ int   g_col[NE];
__device__ int   g_bsum[NSB];
__device__ float g_agg[(size_t)NN * DH];
__device__ float g_h1[(size_t)NN * DH];
__device__ float g_h2[(size_t)NN * DH];
__device__ __nv_bfloat16 g_featb[(size_t)NN * DH];
__device__ __nv_bfloat16 g_h1b[(size_t)NN * DH];

// ---------------- tf32 warp-MMA helpers ----------------
__device__ __forceinline__ uint32_t tf32_of(float f) {
    uint32_t r;
    asm("cvt.rna.tf32.f32 %0, %1;" : "=r"(r) : "f"(f));
    return r;
}
__device__ __forceinline__ void mma_tf32(float (&c)[4], const uint32_t (&a)[4],
                                         const uint32_t (&b)[2]) {
    asm volatile(
        "mma.sync.aligned.m16n8k8.row.col.f32.tf32.tf32.f32 "
        "{%0,%1,%2,%3}, {%4,%5,%6,%7}, {%8,%9}, {%0,%1,%2,%3};"
        : "+f"(c[0]), "+f"(c[1]), "+f"(c[2]), "+f"(c[3])
        : "r"(a[0]), "r"(a[1]), "r"(a[2]), "r"(a[3]), "r"(b[0]), "r"(b[1]));
}

// ---------------- graph build ----------------
__global__ void k_zero() {
    int i = blockIdx.x * blockDim.x + threadIdx.x;
    if (i < NN) { g_deg[i] = 0; g_cur[i] = 0; }
}

__global__ void k_count(const int* __restrict__ dst) {
    int e = blockIdx.x * blockDim.x + threadIdx.x;
    if (e < NE) atomicAdd(&g_deg[dst[e]], 1);
}

// phase A: per-block chunk sums
__global__ void k_scanA() {
    __shared__ int wsum[32];
    int tid = threadIdx.x, lane = tid & 31, wid = tid >> 5;
    int i = blockIdx.x * SBLK + tid;
    int v = (i < NN) ? g_deg[i] : 0;
    int x = v;
#pragma unroll
    for (int o = 16; o > 0; o >>= 1) x += __shfl_xor_sync(0xffffffffu, x, o);
    if (lane == 0) wsum[wid] = x;
    __syncthreads();
    if (wid == 0) {
        int y = (lane < SBLK / 32) ? wsum[lane] : 0;
#pragma unroll
        for (int o = 16; o > 0; o >>= 1) y += __shfl_xor_sync(0xffffffffu, y, o);
        if (lane == 0) g_bsum[blockIdx.x] = y;
    }
}

// phase B: single small block scans NSB block sums (exclusive), writes total
__global__ void k_scanB() {
    __shared__ int s[NSB];
    int tid = threadIdx.x;           // 128 threads
    if (tid < NSB) s[tid] = g_bsum[tid];
    __syncthreads();
    if (tid == 0) {
        int acc = 0;
        for (int b = 0; b < NSB; b++) { int t = s[b]; s[b] = acc; acc += t; }
        g_rp[NN] = acc;
    }
    __syncthreads();
    if (tid < NSB) g_bsum[tid] = s[tid];
}

// phase C: per-block exclusive scan + offset, write rp/inv
__global__ void k_scanC() {
    __shared__ int wsum[32];
    int tid = threadIdx.x, lane = tid & 31, wid = tid >> 5;
    int i = blockIdx.x * SBLK + tid;
    int v = (i < NN) ? g_deg[i] : 0;
    int x = v;
#pragma unroll
    for (int o = 1; o < 32; o <<= 1) {
        int y = __shfl_up_sync(0xffffffffu, x, o);
        if (lane >= o) x += y;
    }
    if (lane == 31) wsum[wid] = x;
    __syncthreads();
    if (wid == 0) {
        int y = (lane < SBLK / 32) ? wsum[lane] : 0;
        int z = y;
#pragma unroll
        for (int o = 1; o < 32; o <<= 1) {
            int t = __shfl_up_sync(0xffffffffu, z, o);
            if (lane >= o) z += t;
        }
        if (lane < SBLK / 32) wsum[lane] = z - y;   // exclusive warp offsets
    }
    __syncthreads();
    if (i < NN) {
        g_rp[i]  = g_bsum[blockIdx.x] + wsum[wid] + x - v;
        g_inv[i] = 1.0f / (float)(v > 1 ? v : 1);
    }
}

__global__ void k_fill(const int* __restrict__ src, const int* __restrict__ dst) {
    int e = blockIdx.x * blockDim.x + threadIdx.x;
    if (e < NE) {
        int d = dst[e];
        int p = atomicAdd(&g_cur[d], 1);
        g_col[g_rp[d] + p] = src[e];
    }
}

// ---------------- fp32 -> bf16 conversion ----------------
__global__ void k_tobf16(const float4* __restrict__ x, __nv_bfloat162* __restrict__ y) {
    int i = blockIdx.x * blockDim.x + threadIdx.x;
    if (i < NN * DH / 4) {
        float4 v = x[i];
        y[2 * i]     = __floats2bfloat162_rn(v.x, v.y);
        y[2 * i + 1] = __floats2bfloat162_rn(v.z, v.w);
    }
}

// ---------------- mean aggregation from bf16: one warp per node ----------------
__global__ void k_agg_bf(const __nv_bfloat16* __restrict__ xb, float* __restrict__ out) {
    int gw = (blockIdx.x * blockDim.x + threadIdx.x) >> 5;
    if (gw >= NN) return;
    int lane = threadIdx.x & 31;
    int s = g_rp[gw], e = g_rp[gw + 1];
    const uint2* xv = (const uint2*)xb;   // row = 32 uint2
    float4 acc = make_float4(0.f, 0.f, 0.f, 0.f);
    int j = s;
    for (; j + 4 <= e; j += 4) {
        int n0 = g_col[j], n1 = g_col[j + 1], n2 = g_col[j + 2], n3 = g_col[j + 3];
        uint2 u0 = xv[n0 * 32 + lane];
        uint2 u1 = xv[n1 * 32 + lane];
        uint2 u2 = xv[n2 * 32 + lane];
        uint2 u3 = xv[n3 * 32 + lane];
#pragma unroll
        for (int q = 0; q < 4; q++) {
            uint2 u = q == 0 ? u0 : q == 1 ? u1 : q == 2 ? u2 : u3;
            float2 lo = __bfloat1622float2(*(__nv_bfloat162*)&u.x);
            float2 hi = __bfloat1622float2(*(__nv_bfloat162*)&u.y);
            acc.x += lo.x; acc.y += lo.y; acc.z += hi.x; acc.w += hi.y;
        }
    }
    for (; j < e; j++) {
        uint2 u = xv[g_col[j] * 32 + lane];
        float2 lo = __bfloat1622float2(*(__nv_bfloat162*)&u.x);
        float2 hi = __bfloat1622float2(*(__nv_bfloat162*)&u.y);
        acc.x += lo.x; acc.y += lo.y; acc.z += hi.x; acc.w += hi.y;
    }
    float id = g_inv[gw];
    acc.x *= id; acc.y *= id; acc.z *= id; acc.w *= id;
    ((float4*)out)[gw * 32 + lane] = acc;
}

// ---------------- Y[M,128] = relu(A[M,128] @ W^T + b) via tf32 warp-MMA ----------------
__global__ void k_gemm128(const float* __restrict__ A, const float* __restrict__ W,
                          const float* __restrict__ bias, float* __restrict__ Y,
                          __nv_bfloat16* __restrict__ Yb) {
    extern __shared__ float sm[];
    float* As = sm;               // [64][132]
    float* Bs = sm + 64 * 132;    // [128][132]
    int tid = threadIdx.x;
    int row0 = blockIdx.x * 64;

    const float4* W4 = (const float4*)W;
    for (int idx = tid; idx < 128 * 32; idx += 256) {
        int n = idx >> 5, kq = idx & 31;
        float4 v = W4[idx];
        *(float4*)&Bs[n * 132 + kq * 4] = v;
    }
    const float4* A4 = (const float4*)A;
    for (int idx = tid; idx < 64 * 32; idx += 256) {
        int r = idx >> 5, kq = idx & 31;
        int gr = row0 + r;
        float4 v = (gr < NN) ? A4[(size_t)gr * 32 + kq] : make_float4(0.f, 0.f, 0.f, 0.f);
        *(float4*)&As[r * 132 + kq * 4] = v;
    }
    __syncthreads();

    int warp = tid >> 5, lane = tid & 31;
    int warpM = warp & 1;
    int warpN = warp >> 1;
    int g = lane >> 2, tg = lane & 3;

    float acc[2][4][4];
#pragma unroll
    for (int t = 0; t < 2; t++)
#pragma unroll
        for (int j = 0; j < 4; j++)
#pragma unroll
            for (int q = 0; q < 4; q++) acc[t][j][q] = 0.f;

#pragma unroll
    for (int k0 = 0; k0 < 128; k0 += 8) {
        uint32_t a[2][4], b[4][2];
#pragma unroll
        for (int t = 0; t < 2; t++) {
            int r = warpM * 32 + t * 16 + g;
            a[t][0] = tf32_of(As[r * 132 + k0 + tg]);
            a[t][1] = tf32_of(As[(r + 8) * 132 + k0 + tg]);
            a[t][2] = tf32_of(As[r * 132 + k0 + tg + 4]);
            a[t][3] = tf32_of(As[(r + 8) * 132 + k0 + tg + 4]);
        }
#pragma unroll
        for (int j = 0; j < 4; j++) {
            int n = warpN * 32 + j * 8 + g;
            b[j][0] = tf32_of(Bs[n * 132 + k0 + tg]);
            b[j][1] = tf32_of(Bs[n * 132 + k0 + tg + 4]);
        }
#pragma unroll
        for (int t = 0; t < 2; t++)
#pragma unroll
            for (int j = 0; j < 4; j++) mma_tf32(acc[t][j], a[t], b[j]);
    }

#pragma unroll
    for (int t = 0; t < 2; t++) {
        int r = row0 + warpM * 32 + t * 16 + g;
#pragma unroll
        for (int j = 0; j < 4; j++) {
            int c = warpN * 32 + j * 8 + tg * 2;
            float bc0 = bias[c], bc1 = bias[c + 1];
            if (r < NN) {
                float2 o;
                o.x = fmaxf(acc[t][j][0] + bc0, 0.f);
                o.y = fmaxf(acc[t][j][1] + bc1, 0.f);
                *(float2*)&Y[(size_t)r * 128 + c] = o;
                if (Yb) *(__nv_bfloat162*)&Yb[(size_t)r * 128 + c] = __floats2bfloat162_rn(o.x, o.y);
            }
            if (r + 8 < NN) {
                float2 o;
                o.x = fmaxf(acc[t][j][2] + bc0, 0.f);
                o.y = fmaxf(acc[t][j][3] + bc1, 0.f);
                *(float2*)&Y[(size_t)(r + 8) * 128 + c] = o;
                if (Yb) *(__nv_bfloat162*)&Yb[(size_t)(r + 8) * 128 + c] = __floats2bfloat162_rn(o.x, o.y);
            }
        }
    }
}

// ---------------- logits + log_softmax via tf32 warp-MMA ----------------
__global__ void k_logits(const float* __restrict__ Wl, const float* __restrict__ bl,
                         float* __restrict__ out) {
    extern __shared__ float sm[];
    float* As = sm;               // [128][132]
    float* Ws = sm + 128 * 132;   // [64][132]
    int tid = threadIdx.x;
    int row0 = blockIdx.x * 128;
    int warp = tid >> 5, lane = tid & 31;
    int warpM = warp & 3;
    int warpN = warp >> 2;
    int g = lane >> 2, tg = lane & 3;

    float acc[2][4][4];
#pragma unroll
    for (int t = 0; t < 2; t++)
#pragma unroll
        for (int j = 0; j < 4; j++)
#pragma unroll
            for (int q = 0; q < 4; q++) acc[t][j][q] = 0.f;

    const float4* Wl4 = (const float4*)Wl;
    for (int ph = 0; ph < 2; ph++) {
        const float* X = ph ? g_h2 : g_h1;
        const float4* X4 = (const float4*)X;
        __syncthreads();
        for (int idx = tid; idx < 128 * 32; idx += 256) {
            int r = idx >> 5, kq = idx & 31;
            int gr = row0 + r;
            float4 v = (gr < NN) ? X4[(size_t)gr * 32 + kq] : make_float4(0.f, 0.f, 0.f, 0.f);
            *(float4*)&As[r * 132 + kq * 4] = v;
        }
        for (int idx = tid; idx < 64 * 32; idx += 256) {
            int n = idx >> 5, kq = idx & 31;
            float4 v = Wl4[n * 64 + ph * 32 + kq];
            *(float4*)&Ws[n * 132 + kq * 4] = v;
        }
        __syncthreads();

#pragma unroll
        for (int k0 = 0; k0 < 128; k0 += 8) {
            uint32_t a[2][4], b[4][2];
#pragma unroll
            for (int t = 0; t < 2; t++) {
                int r = warpM * 32 + t * 16 + g;
                a[t][0] = tf32_of(As[r * 132 + k0 + tg]);
                a[t][1] = tf32_of(As[(r + 8) * 132 + k0 + tg]);
                a[t][2] = tf32_of(As[r * 132 + k0 + tg + 4]);
                a[t][3] = tf32_of(As[(r + 8) * 132 + k0 + tg + 4]);
            }
#pragma unroll
            for (int j = 0; j < 4; j++) {
                int n = warpN * 32 + j * 8 + g;
                b[j][0] = tf32_of(Ws[n * 132 + k0 + tg]);
                b[j][1] = tf32_of(Ws[n * 132 + k0 + tg + 4]);
            }
#pragma unroll
            for (int t = 0; t < 2; t++)
#pragma unroll
                for (int j = 0; j < 4; j++) mma_tf32(acc[t][j], a[t], b[j]);
        }
    }

    __syncthreads();
    float* Ls = sm;
#pragma unroll
    for (int t = 0; t < 2; t++) {
        int r = warpM * 32 + t * 16 + g;
#pragma unroll
        for (int j = 0; j < 4; j++) {
            int c = warpN * 32 + j * 8 + tg * 2;
            float bc0 = bl[c], bc1 = bl[c + 1];
            Ls[r * 68 + c]           = acc[t][j][0] + bc0;
            Ls[r * 68 + c + 1]       = acc[t][j][1] + bc1;
            Ls[(r + 8) * 68 + c]     = acc[t][j][2] + bc0;
            Ls[(r + 8) * 68 + c + 1] = acc[t][j][3] + bc1;
        }
    }
    __syncthreads();

    for (int rr = warp * 16; rr < warp * 16 + 16; rr++) {
        float v0 = Ls[rr * 68 + lane];
        float v1 = Ls[rr * 68 + 32 + lane];
        float m = fmaxf(v0, v1);
#pragma unroll
        for (int o = 16; o > 0; o >>= 1) m = fmaxf(m, __shfl_xor_sync(0xffffffffu, m, o));
        float s = expf(v0 - m) + expf(v1 - m);
#pragma unroll
        for (int o = 16; o > 0; o >>= 1) s += __shfl_xor_sync(0xffffffffu, s, o);
        float lse = m + logf(s);
        int gr = row0 + rr;
        if (gr < NN) {
            out[(size_t)gr * 64 + lane]      = v0 - lse;
            out[(size_t)gr * 64 + 32 + lane] = v1 - lse;
        }
    }
}

extern "C" void kernel_launch(void* const* d_in, const int* in_sizes, int n_in,
                              void* d_out, int out_size) {
    const float* feat = (const float*)d_in[0];
    const int*   src  = (const int*)d_in[1];
    const int*   dst  = (const int*)d_in[2];
    const float* W1   = (const float*)d_in[3];
    const float* b1   = (const float*)d_in[4];
    const float* W2   = (const float*)d_in[5];
    const float* b2   = (const float*)d_in[6];
    const float* Wl   = (const float*)d_in[7];
    const float* bl   = (const float*)d_in[8];
    float* out = (float*)d_out;

    void *p_agg, *p_h1, *p_h2, *p_fb, *p_h1b;
    cudaGetSymbolAddress(&p_agg, g_agg);
    cudaGetSymbolAddress(&p_h1,  g_h1);
    cudaGetSymbolAddress(&p_h2,  g_h2);
    cudaGetSymbolAddress(&p_fb,  g_featb);
    cudaGetSymbolAddress(&p_h1b, g_h1b);

    const int SMEM_GEMM   = (64 * 132 + 128 * 132) * 4;   // 101376
    const int SMEM_LOGITS = (128 * 132 + 64 * 132) * 4;   // 101376
    cudaFuncSetAttribute(k_gemm128, cudaFuncAttributeMaxDynamicSharedMemorySize, SMEM_GEMM);
    cudaFuncSetAttribute(k_logits,  cudaFuncAttributeMaxDynamicSharedMemorySize, SMEM_LOGITS);

    // graph build (per-launch, deterministic work)
    k_zero <<<(NN + 255) / 256, 256>>>();
    k_count<<<(NE + 255) / 256, 256>>>(dst);
    k_scanA<<<NSB, SBLK>>>();
    k_scanB<<<1, 128>>>();
    k_scanC<<<NSB, SBLK>>>();
    k_fill <<<(NE + 255) / 256, 256>>>(src, dst);

    // feat -> bf16
    k_tobf16<<<(NN * DH / 4 + 255) / 256, 256>>>((const float4*)feat, (__nv_bfloat162*)p_fb);

    // layer 1
    k_agg_bf<<<(NN * 32 + 255) / 256, 256>>>((const __nv_bfloat16*)p_fb, (float*)p_agg);
    k_gemm128<<<(NN + 63) / 64, 256, SMEM_GEMM>>>((const float*)p_agg, W1, b1,
                                                  (float*)p_h1, (__nv_bfloat16*)p_h1b);

    // layer 2
    k_agg_bf<<<(NN * 32 + 255) / 256, 256>>>((const __nv_bfloat16*)p_h1b, (float*)p_agg);
    k_gemm128<<<(NN + 63) / 64, 256, SMEM_GEMM>>>((const float*)p_agg, W2, b2,
                                                  (float*)p_h2, (__nv_bfloat16*)0);

    // logits + log_softmax
    k_logits<<<(NN + 127) / 128, 256, SMEM_LOGITS>>>(Wl, bl, out);
}